// round 4
// baseline (speedup 1.0000x reference)
#include <cuda_runtime.h>
#include <math.h>

#define S_LEN   2048
#define DK      64
#define MQ      16          // q rows per CTA
#define NK      256         // k chunk
#define SPITCH  2052        // score row pitch (floats): mult of 4
#define KPITCH  65          // K smem row pitch (floats): odd => conflict-free strided reads
#define NEGV    (-1000000000.0f)

// smem layout (floats):
//   scoreS : [MQ][SPITCH]           = 32832
//   Ks/Vs  : [NK][KPITCH] (>= Vs [NK][64], >= red [4][MQ][DK]) = 16640
//   Qs     : [DK][MQ]               = 1024
#define SMEM_FLOATS (MQ*SPITCH + NK*KPITCH + DK*MQ)

__global__ __launch_bounds__(256, 1)
void attn_fused_kernel(const float* __restrict__ Q, const float* __restrict__ K,
                       const float* __restrict__ V, const int* __restrict__ M,
                       float* __restrict__ ctx, float* __restrict__ prob)
{
    extern __shared__ float sm[];
    float* scoreS = sm;                       // [16][2052]
    float* Ks     = sm + MQ * SPITCH;         // [256][65], reused as Vs[256][64] and red[4][16][64]
    float* Qs     = Ks + NK * KPITCH;         // [64][16]

    const int tid = threadIdx.x;
    const int bh  = blockIdx.y;               // 0..31
    const int b   = bh >> 4;
    const int q0  = blockIdx.x * MQ;

    const float* Qg = Q + ((size_t)bh * S_LEN + q0) * DK;
    const float* Kg = K + (size_t)bh * S_LEN * DK;
    const float* Vg = V + (size_t)bh * S_LEN * DK;
    const int*   Mg = M + (size_t)b * S_LEN * S_LEN + (size_t)q0 * S_LEN;
    float* Pg = prob + ((size_t)bh * S_LEN + q0) * S_LEN;
    float* Cg = ctx  + ((size_t)bh * S_LEN + q0) * DK;

    // ---- load Q tile transposed: Qs[d][q] ----
    for (int i = tid; i < MQ * DK; i += 256) {
        int q = i >> 6, d = i & 63;
        Qs[d * MQ + q] = Qg[q * DK + d];
    }

    // ================= Phase 1: S = mask(QK^T / 8) =================
    const int qt = tid >> 6;    // 0..3  (4 q rows each)
    const int kt = tid & 63;    // 0..63 (k cols kt, kt+64, kt+128, kt+192 of chunk)

    for (int kc = 0; kc < S_LEN / NK; kc++) {
        __syncthreads();
        {   // stage K chunk [256][64] -> Ks[k][d], pitch 65
            const float4* src = (const float4*)(Kg + (size_t)kc * NK * DK);
            #pragma unroll
            for (int i = 0; i < 16; i++) {
                int idx = tid + 256 * i;
                float4 v = src[idx];
                int k = idx >> 4, d4 = idx & 15;
                float* dst = &Ks[k * KPITCH + d4 * 4];
                dst[0] = v.x; dst[1] = v.y; dst[2] = v.z; dst[3] = v.w;
            }
        }
        __syncthreads();

        // prefetch mask values (int32; latency hidden by d-loop)
        int msk[4][4];
        #pragma unroll
        for (int qi = 0; qi < 4; qi++)
            #pragma unroll
            for (int j = 0; j < 4; j++)
                msk[qi][j] = Mg[(size_t)(qt*4+qi) * S_LEN + kc*NK + kt + 64*j];

        float acc[4][4];
        #pragma unroll
        for (int qi = 0; qi < 4; qi++)
            #pragma unroll
            for (int j = 0; j < 4; j++) acc[qi][j] = 0.0f;

        const float* kr0 = &Ks[(kt      ) * KPITCH];
        const float* kr1 = &Ks[(kt +  64) * KPITCH];
        const float* kr2 = &Ks[(kt + 128) * KPITCH];
        const float* kr3 = &Ks[(kt + 192) * KPITCH];

        #pragma unroll 16
        for (int d = 0; d < DK; d++) {
            float4 qv = *(const float4*)(Qs + d * MQ + (qt << 2));   // warp-broadcast
            float k0 = kr0[d], k1 = kr1[d], k2 = kr2[d], k3 = kr3[d];
            acc[0][0] = fmaf(qv.x, k0, acc[0][0]);
            acc[0][1] = fmaf(qv.x, k1, acc[0][1]);
            acc[0][2] = fmaf(qv.x, k2, acc[0][2]);
            acc[0][3] = fmaf(qv.x, k3, acc[0][3]);
            acc[1][0] = fmaf(qv.y, k0, acc[1][0]);
            acc[1][1] = fmaf(qv.y, k1, acc[1][1]);
            acc[1][2] = fmaf(qv.y, k2, acc[1][2]);
            acc[1][3] = fmaf(qv.y, k3, acc[1][3]);
            acc[2][0] = fmaf(qv.z, k0, acc[2][0]);
            acc[2][1] = fmaf(qv.z, k1, acc[2][1]);
            acc[2][2] = fmaf(qv.z, k2, acc[2][2]);
            acc[2][3] = fmaf(qv.z, k3, acc[2][3]);
            acc[3][0] = fmaf(qv.w, k0, acc[3][0]);
            acc[3][1] = fmaf(qv.w, k1, acc[3][1]);
            acc[3][2] = fmaf(qv.w, k2, acc[3][2]);
            acc[3][3] = fmaf(qv.w, k3, acc[3][3]);
        }

        #pragma unroll
        for (int qi = 0; qi < 4; qi++) {
            int q = qt*4 + qi;
            #pragma unroll
            for (int j = 0; j < 4; j++) {
                int k = kc*NK + kt + 64*j;
                float s = acc[qi][j] * 0.125f;
                if (msk[qi][j]) s = NEGV;
                scoreS[q * SPITCH + k] = s;      // lanes: distinct banks (kt consecutive)
            }
        }
    }
    __syncthreads();

    // ================= Phase 2: softmax rows, write P (smem + gmem) =================
    {
        const int warp = tid >> 5, lane = tid & 31;
        #pragma unroll
        for (int rr = 0; rr < 2; rr++) {
            int q = warp + 8 * rr;
            float v[64];
            float m = -3.4e38f;
            #pragma unroll
            for (int i = 0; i < 16; i++) {
                float4 t = *(const float4*)&scoreS[q * SPITCH + lane*4 + 128*i];
                v[4*i+0] = t.x; v[4*i+1] = t.y; v[4*i+2] = t.z; v[4*i+3] = t.w;
                m = fmaxf(m, fmaxf(fmaxf(t.x, t.y), fmaxf(t.z, t.w)));
            }
            #pragma unroll
            for (int o = 16; o > 0; o >>= 1) m = fmaxf(m, __shfl_xor_sync(0xffffffffu, m, o));
            float ssum = 0.0f;
            #pragma unroll
            for (int i = 0; i < 64; i++) { v[i] = __expf(v[i] - m); ssum += v[i]; }
            #pragma unroll
            for (int o = 16; o > 0; o >>= 1) ssum += __shfl_xor_sync(0xffffffffu, ssum, o);
            float inv = 1.0f / ssum;
            #pragma unroll
            for (int i = 0; i < 16; i++) {
                float4 t = make_float4(v[4*i]*inv, v[4*i+1]*inv, v[4*i+2]*inv, v[4*i+3]*inv);
                *(float4*)&scoreS[q * SPITCH + lane*4 + 128*i] = t;
                *(float4*)&Pg[(size_t)q * S_LEN + lane*4 + 128*i] = t;   // coalesced 553MB write, once
            }
        }
    }

    // ================= Phase 3: C = P @ V (4-way split-k) =================
    const int g   = tid >> 6;          // k-split group 0..3
    const int qt3 = (tid >> 4) & 3;    // q tile 0..3
    const int dt  = tid & 15;          // d tile 0..15

    float cacc[4][4];
    #pragma unroll
    for (int qi = 0; qi < 4; qi++)
        #pragma unroll
        for (int c = 0; c < 4; c++) cacc[qi][c] = 0.0f;

    for (int kc = 0; kc < S_LEN / NK; kc++) {
        __syncthreads();
        {   // stage V chunk [256][64], natural layout, pure float4 copy
            const float4* src = (const float4*)(Vg + (size_t)kc * NK * DK);
            float4* dst = (float4*)Ks;
            #pragma unroll
            for (int i = 0; i < 16; i++) dst[tid + 256*i] = src[tid + 256*i];
        }
        __syncthreads();

        const float* Pr0 = &scoreS[(qt3*4+0) * SPITCH + kc*NK + (g<<6)];
        const float* Pr1 = &scoreS[(qt3*4+1) * SPITCH + kc*NK + (g<<6)];
        const float* Pr2 = &scoreS[(qt3*4+2) * SPITCH + kc*NK + (g<<6)];
        const float* Pr3 = &scoreS[(qt3*4+3) * SPITCH + kc*NK + (g<<6)];

        #pragma unroll 8
        for (int i = 0; i < 64; i++) {
            float4 vv = *(const float4*)(Ks + ((g<<6)+i) * 64 + (dt<<2));
            float p0 = Pr0[i], p1 = Pr1[i], p2 = Pr2[i], p3 = Pr3[i];
            cacc[0][0] = fmaf(p0, vv.x, cacc[0][0]);
            cacc[0][1] = fmaf(p0, vv.y, cacc[0][1]);
            cacc[0][2] = fmaf(p0, vv.z, cacc[0][2]);
            cacc[0][3] = fmaf(p0, vv.w, cacc[0][3]);
            cacc[1][0] = fmaf(p1, vv.x, cacc[1][0]);
            cacc[1][1] = fmaf(p1, vv.y, cacc[1][1]);
            cacc[1][2] = fmaf(p1, vv.z, cacc[1][2]);
            cacc[1][3] = fmaf(p1, vv.w, cacc[1][3]);
            cacc[2][0] = fmaf(p2, vv.x, cacc[2][0]);
            cacc[2][1] = fmaf(p2, vv.y, cacc[2][1]);
            cacc[2][2] = fmaf(p2, vv.z, cacc[2][2]);
            cacc[2][3] = fmaf(p2, vv.w, cacc[2][3]);
            cacc[3][0] = fmaf(p3, vv.x, cacc[3][0]);
            cacc[3][1] = fmaf(p3, vv.y, cacc[3][1]);
            cacc[3][2] = fmaf(p3, vv.z, cacc[3][2]);
            cacc[3][3] = fmaf(p3, vv.w, cacc[3][3]);
        }
    }
    __syncthreads();

    // cross-group reduction via smem (reuse Ks region)
    float* red = Ks;   // [4][16][64]
    #pragma unroll
    for (int qi = 0; qi < 4; qi++)
        #pragma unroll
        for (int c = 0; c < 4; c++)
            red[(g*MQ + qt3*4 + qi) * DK + (dt<<2) + c] = cacc[qi][c];
    __syncthreads();
    {
        int q = tid >> 4, d4 = tid & 15;
        float o0 = 0.f, o1 = 0.f, o2 = 0.f, o3 = 0.f;
        #pragma unroll
        for (int gg = 0; gg < 4; gg++) {
            const float* r = &red[(gg*MQ + q) * DK + (d4<<2)];
            o0 += r[0]; o1 += r[1]; o2 += r[2]; o3 += r[3];
        }
        *(float4*)&Cg[q * DK + (d4<<2)] = make_float4(o0, o1, o2, o3);
    }
}

extern "C" void kernel_launch(void* const* d_in, const int* in_sizes, int n_in,
                              void* d_out, int out_size)
{
    const float* Q = (const float*)d_in[0];
    const float* K = (const float*)d_in[1];
    const float* V = (const float*)d_in[2];
    const int*   M = (const int*)d_in[3];     // bool mask widened to int32 by harness

    float* ctx  = (float*)d_out;
    float* prob = ctx + (size_t)2 * 16 * 2048 * 64;   // context first, then attn_prob

    const size_t smem_bytes = (size_t)SMEM_FLOATS * sizeof(float);   // 201,984 B
    cudaFuncSetAttribute(attn_fused_kernel,
                         cudaFuncAttributeMaxDynamicSharedMemorySize, (int)smem_bytes);

    dim3 grid(S_LEN / MQ, 32);   // 128 q-tiles x (B*H)
    attn_fused_kernel<<<grid, 256, smem_bytes>>>(Q, K, V, M, ctx, prob);
}